// round 1
// baseline (speedup 1.0000x reference)
#include <cuda_runtime.h>
#include <cstdint>

#define N_NODES 50000
#define N_EDGES 800000
#define D_IN    16
#define HID     128
#define D_OUT   4
#define N_LAYERS 3
#define LN_EPS  1e-5f

// Scratch (device globals: allocation-free, graph-capturable)
__device__ float g_h  [N_NODES * HID];
__device__ float g_hn [N_NODES * HID];
__device__ float g_agg[N_NODES * HID];
__device__ float g_deg[N_NODES];
__device__ float g_inv[N_NODES];

// ---------------------------------------------------------------------------
// Degree / normalizer
// ---------------------------------------------------------------------------
__global__ void k_zero_deg() {
    int i = blockIdx.x * blockDim.x + threadIdx.x;
    if (i < N_NODES) g_deg[i] = 0.0f;
}

__global__ void k_count(const int* __restrict__ dst) {
    int e = blockIdx.x * blockDim.x + threadIdx.x;
    if (e < N_EDGES) atomicAdd(&g_deg[dst[e]], 1.0f);
}

__global__ void k_invdeg() {
    int i = blockIdx.x * blockDim.x + threadIdx.x;
    if (i < N_NODES) g_inv[i] = 1.0f / fmaxf(g_deg[i], 1.0f);
}

// ---------------------------------------------------------------------------
// h = x @ W_in + b_in    (50000 x 16 @ 16 x 128)
// block = 256 threads -> 2 rows x 128 cols, W_in cached in smem
// ---------------------------------------------------------------------------
__global__ void k_in_gemm(const float* __restrict__ x,
                          const float* __restrict__ W,
                          const float* __restrict__ b) {
    __shared__ float Ws[D_IN * HID];
    int tid = threadIdx.x;
    for (int i = tid; i < D_IN * HID; i += blockDim.x) Ws[i] = W[i];
    __syncthreads();

    int row = blockIdx.x * 2 + (tid >> 7);
    int col = tid & 127;
    if (row >= N_NODES) return;
    const float* xr = x + row * D_IN;
    float acc = b[col];
#pragma unroll
    for (int k = 0; k < D_IN; k++) acc += xr[k] * Ws[k * HID + col];
    g_h[(size_t)row * HID + col] = acc;
}

// ---------------------------------------------------------------------------
// LayerNorm: hn = LN(h) * g + b, and zero agg (fused)
// one warp per row; lane handles a float4 (cols lane*4 .. lane*4+3)
// ---------------------------------------------------------------------------
__global__ void k_ln(const float* __restrict__ g, const float* __restrict__ b) {
    int warp = (blockIdx.x * blockDim.x + threadIdx.x) >> 5;
    int lane = threadIdx.x & 31;
    if (warp >= N_NODES) return;

    float4 v = ((const float4*)(g_h + (size_t)warp * HID))[lane];
    float s = v.x + v.y + v.z + v.w;
#pragma unroll
    for (int o = 16; o; o >>= 1) s += __shfl_xor_sync(0xFFFFFFFFu, s, o);
    float mu = s * (1.0f / HID);

    float dx = v.x - mu, dy = v.y - mu, dz = v.z - mu, dw = v.w - mu;
    float q = dx * dx + dy * dy + dz * dz + dw * dw;
#pragma unroll
    for (int o = 16; o; o >>= 1) q += __shfl_xor_sync(0xFFFFFFFFu, q, o);
    float rs = rsqrtf(q * (1.0f / HID) + LN_EPS);

    int c = lane * 4;
    float4 gg = *(const float4*)(g + c);
    float4 bb = *(const float4*)(b + c);
    float4 o4;
    o4.x = dx * rs * gg.x + bb.x;
    o4.y = dy * rs * gg.y + bb.y;
    o4.z = dz * rs * gg.z + bb.z;
    o4.w = dw * rs * gg.w + bb.w;
    ((float4*)(g_hn + (size_t)warp * HID))[lane] = o4;
    ((float4*)(g_agg + (size_t)warp * HID))[lane] = make_float4(0.f, 0.f, 0.f, 0.f);
}

// ---------------------------------------------------------------------------
// Scatter-add: agg[dst] += hn[src]   (one warp per edge, red.global.add.v4)
// ---------------------------------------------------------------------------
__global__ void k_scatter(const int* __restrict__ src, const int* __restrict__ dst) {
    int warp = (blockIdx.x * blockDim.x + threadIdx.x) >> 5;
    int lane = threadIdx.x & 31;
    if (warp >= N_EDGES) return;
    int s = src[warp];
    int d = dst[warp];
    float4 v = ((const float4*)(g_hn + (size_t)s * HID))[lane];
    float* q = g_agg + (size_t)d * HID + lane * 4;
    asm volatile("red.global.add.v4.f32 [%0], {%1, %2, %3, %4};"
                 :: "l"(q), "f"(v.x), "f"(v.y), "f"(v.z), "f"(v.w)
                 : "memory");
}

// ---------------------------------------------------------------------------
// Layer update GEMM: h = relu(h + [agg*inv | hn] @ [Wl ; Wr] + bl)
// A: [N, 256] virtual, B: [256, 128]. Tiled: BM=64, BN=128 (full), BK=16.
// 256 threads, each computes an 8x4 microtile.
// ---------------------------------------------------------------------------
#define BM 64
#define BK 16

__global__ void k_layer(const float* __restrict__ Wl,
                        const float* __restrict__ Wr,
                        const float* __restrict__ bl) {
    __shared__ float As[BK][BM + 1];   // padded: conflict-free transposed store
    __shared__ float Bs[BK][HID];

    int tid = threadIdx.x;
    int tx = tid & 31;   // col group: cols tx*4 .. tx*4+3
    int ty = tid >> 5;   // row group: rows ty*8 .. ty*8+7
    int m0 = blockIdx.x * BM;

    float acc[8][4];
#pragma unroll
    for (int i = 0; i < 8; i++)
#pragma unroll
        for (int j = 0; j < 4; j++) acc[i][j] = 0.0f;

    for (int kt = 0; kt < 2 * HID; kt += BK) {
        // Load A tile (64 x 16): 4 elements per thread
#pragma unroll
        for (int i = 0; i < 4; i++) {
            int idx = tid + i * 256;
            int r = idx >> 4;
            int k = idx & 15;
            int row = m0 + r;
            int kk = kt + k;
            float v = 0.0f;
            if (row < N_NODES) {
                if (kk < HID) v = g_agg[(size_t)row * HID + kk] * g_inv[row];
                else          v = g_hn[(size_t)row * HID + (kk - HID)];
            }
            As[k][r] = v;
        }
        // Load B tile (16 x 128): 8 elements per thread
#pragma unroll
        for (int i = 0; i < 8; i++) {
            int idx = tid + i * 256;
            int k = idx >> 7;
            int n = idx & 127;
            int kk = kt + k;
            Bs[k][n] = (kk < HID) ? Wl[kk * HID + n] : Wr[(kk - HID) * HID + n];
        }
        __syncthreads();

#pragma unroll
        for (int k = 0; k < BK; k++) {
            float a[8];
#pragma unroll
            for (int i = 0; i < 8; i++) a[i] = As[k][ty * 8 + i];  // warp-broadcast
            float4 b4 = *(const float4*)&Bs[k][tx * 4];
#pragma unroll
            for (int i = 0; i < 8; i++) {
                acc[i][0] += a[i] * b4.x;
                acc[i][1] += a[i] * b4.y;
                acc[i][2] += a[i] * b4.z;
                acc[i][3] += a[i] * b4.w;
            }
        }
        __syncthreads();
    }

    // Epilogue: residual + bias + relu, in place into g_h
    float4 bb = *(const float4*)(bl + tx * 4);
#pragma unroll
    for (int i = 0; i < 8; i++) {
        int row = m0 + ty * 8 + i;
        if (row >= N_NODES) continue;
        float4 hv = *(const float4*)(g_h + (size_t)row * HID + tx * 4);
        float4 o;
        o.x = fmaxf(hv.x + acc[i][0] + bb.x, 0.0f);
        o.y = fmaxf(hv.y + acc[i][1] + bb.y, 0.0f);
        o.z = fmaxf(hv.z + acc[i][2] + bb.z, 0.0f);
        o.w = fmaxf(hv.w + acc[i][3] + bb.w, 0.0f);
        *(float4*)(g_h + (size_t)row * HID + tx * 4) = o;
    }
}

// ---------------------------------------------------------------------------
// out = h @ W_out + b_out   (50000 x 128 @ 128 x 4), one warp per node
// ---------------------------------------------------------------------------
__global__ void k_out(const float* __restrict__ Wo,
                      const float* __restrict__ bo,
                      float* __restrict__ out) {
    __shared__ float Ws[HID * D_OUT];
    int tid = threadIdx.x;
    for (int i = tid; i < HID * D_OUT; i += blockDim.x) Ws[i] = Wo[i];
    __syncthreads();

    int warp = (blockIdx.x * blockDim.x + tid) >> 5;
    int lane = tid & 31;
    if (warp >= N_NODES) return;

    const float* hr = g_h + (size_t)warp * HID;
    float a0 = 0.f, a1 = 0.f, a2 = 0.f, a3 = 0.f;
#pragma unroll
    for (int t = 0; t < 4; t++) {
        int k = lane + t * 32;
        float hv = hr[k];
        a0 += hv * Ws[k * D_OUT + 0];
        a1 += hv * Ws[k * D_OUT + 1];
        a2 += hv * Ws[k * D_OUT + 2];
        a3 += hv * Ws[k * D_OUT + 3];
    }
#pragma unroll
    for (int o = 16; o; o >>= 1) {
        a0 += __shfl_xor_sync(0xFFFFFFFFu, a0, o);
        a1 += __shfl_xor_sync(0xFFFFFFFFu, a1, o);
        a2 += __shfl_xor_sync(0xFFFFFFFFu, a2, o);
        a3 += __shfl_xor_sync(0xFFFFFFFFu, a3, o);
    }
    if (lane == 0) {
        float4 r;
        r.x = a0 + bo[0];
        r.y = a1 + bo[1];
        r.z = a2 + bo[2];
        r.w = a3 + bo[3];
        *(float4*)(out + (size_t)warp * D_OUT) = r;
    }
}

// ---------------------------------------------------------------------------
extern "C" void kernel_launch(void* const* d_in, const int* in_sizes, int n_in,
                              void* d_out, int out_size) {
    const float* x     = (const float*)d_in[0];
    const int*   ei    = (const int*)  d_in[1];
    const float* W_in  = (const float*)d_in[2];
    const float* b_in  = (const float*)d_in[3];
    const float* Wl    = (const float*)d_in[4];
    const float* bl    = (const float*)d_in[5];
    const float* Wr    = (const float*)d_in[6];
    const float* ln_g  = (const float*)d_in[7];
    const float* ln_b  = (const float*)d_in[8];
    const float* W_out = (const float*)d_in[9];
    const float* b_out = (const float*)d_in[10];
    float* out = (float*)d_out;

    const int* src = ei;             // edge_index[0]
    const int* dst = ei + N_EDGES;   // edge_index[1]

    k_zero_deg<<<(N_NODES + 255) / 256, 256>>>();
    k_count<<<(N_EDGES + 255) / 256, 256>>>(dst);
    k_invdeg<<<(N_NODES + 255) / 256, 256>>>();

    k_in_gemm<<<N_NODES / 2, 256>>>(x, W_in, b_in);

    for (int l = 0; l < N_LAYERS; l++) {
        k_ln<<<(N_NODES * 32) / 256 + 1, 256>>>(ln_g + l * HID, ln_b + l * HID);
        k_scatter<<<(N_EDGES * 32) / 256, 256>>>(src, dst);
        k_layer<<<(N_NODES + BM - 1) / BM, 256>>>(Wl + l * HID * HID,
                                                  Wr + l * HID * HID,
                                                  bl + l * HID);
    }

    k_out<<<(N_NODES * 32) / 256 + 1, 256>>>(W_out, b_out, out);
}

// round 3
// speedup vs baseline: 2.0049x; 2.0049x over previous
#include <cuda_runtime.h>
#include <cstdint>

#define N_NODES 50000
#define N_EDGES 800000
#define D_IN    16
#define HID     128
#define D_OUT   4
#define N_LAYERS 3
#define LN_EPS  1e-5f

#define SCAN_BLOCKS 196   // ceil(50000/256)

// Scratch (device globals: allocation-free, graph-capturable)
__device__ float g_h   [N_NODES * HID];
__device__ float g_hn  [N_NODES * HID];
__device__ float g_agg [N_NODES * HID];
__device__ float g_inv [N_NODES];
__device__ int   g_cnt [N_NODES];
__device__ int   g_off [N_NODES + 1];
__device__ int   g_cur [N_NODES];
__device__ int   g_bsum[SCAN_BLOCKS];
__device__ int   g_bpre[SCAN_BLOCKS];
__device__ int   g_esrc[N_EDGES];

// ---------------------------------------------------------------------------
// CSR build: histogram -> scan -> fill
// ---------------------------------------------------------------------------
__global__ void k_zero_cnt() {
    int i = blockIdx.x * blockDim.x + threadIdx.x;
    if (i < N_NODES) g_cnt[i] = 0;
}

__global__ void k_count(const int* __restrict__ dst) {
    int e = blockIdx.x * blockDim.x + threadIdx.x;
    if (e < N_EDGES) atomicAdd(&g_cnt[dst[e]], 1);
}

__global__ void k_scan1() {
    __shared__ int s[2][256];
    int b = blockIdx.x, t = threadIdx.x;
    int i = b * 256 + t;
    int v = (i < N_NODES) ? g_cnt[i] : 0;
    s[0][t] = v;
    __syncthreads();
    int p = 0;
#pragma unroll
    for (int off = 1; off < 256; off <<= 1) {
        int nv = s[p][t] + ((t >= off) ? s[p][t - off] : 0);
        s[p ^ 1][t] = nv;
        __syncthreads();
        p ^= 1;
    }
    if (i < N_NODES) g_off[i] = s[p][t] - v;   // exclusive local
    if (t == 255) g_bsum[b] = s[p][255];       // block total
}

__global__ void k_scan2() {
    __shared__ int s[2][256];
    int t = threadIdx.x;
    int v = (t < SCAN_BLOCKS) ? g_bsum[t] : 0;
    s[0][t] = v;
    __syncthreads();
    int p = 0;
#pragma unroll
    for (int off = 1; off < 256; off <<= 1) {
        int nv = s[p][t] + ((t >= off) ? s[p][t - off] : 0);
        s[p ^ 1][t] = nv;
        __syncthreads();
        p ^= 1;
    }
    if (t < SCAN_BLOCKS) g_bpre[t] = s[p][t] - v;  // exclusive
}

__global__ void k_scan3() {
    int i = blockIdx.x * blockDim.x + threadIdx.x;
    if (i < N_NODES) {
        int o = g_off[i] + g_bpre[i >> 8];
        g_off[i] = o;
        g_cur[i] = o;
        g_inv[i] = 1.0f / fmaxf((float)g_cnt[i], 1.0f);
    }
    if (i == 0) g_off[N_NODES] = N_EDGES;
}

__global__ void k_fill(const int* __restrict__ src, const int* __restrict__ dst) {
    int e = blockIdx.x * blockDim.x + threadIdx.x;
    if (e < N_EDGES) {
        int pos = atomicAdd(&g_cur[dst[e]], 1);
        g_esrc[pos] = src[e];
    }
}

// ---------------------------------------------------------------------------
// h = x @ W_in + b_in    (50000 x 16 @ 16 x 128)
// 256 threads handle 16 rows; x tile + W in smem; W-column cached in regs.
// ---------------------------------------------------------------------------
__global__ void k_in_gemm(const float* __restrict__ x,
                          const float* __restrict__ W,
                          const float* __restrict__ b) {
    __shared__ float xs[16][D_IN];
    __shared__ float Ws[D_IN][HID];
    int tid = threadIdx.x;
    int m0 = blockIdx.x * 16;

    // W: 2048 floats, 8 per thread (float4 x2)
#pragma unroll
    for (int i = 0; i < 2; i++) {
        int idx = tid + i * 256;                  // float4 index 0..511
        ((float4*)&Ws[0][0])[idx] = ((const float4*)W)[idx];
    }
    // x tile: 256 floats, 1 per thread
    {
        int r = tid >> 4, k = tid & 15;
        xs[r][k] = x[(size_t)(m0 + r) * D_IN + k];
    }
    __syncthreads();

    int col = tid & 127;
    int rh  = tid >> 7;    // 0/1 -> rows rh*8 .. rh*8+7
    float wc[D_IN];
#pragma unroll
    for (int k = 0; k < D_IN; k++) wc[k] = Ws[k][col];
    float bb = b[col];

#pragma unroll
    for (int r = 0; r < 8; r++) {
        int row = rh * 8 + r;
        float acc = bb;
#pragma unroll
        for (int k = 0; k < D_IN; k++) acc += xs[row][k] * wc[k];
        g_h[(size_t)(m0 + row) * HID + col] = acc;
    }
}

// ---------------------------------------------------------------------------
// LayerNorm: hn = LN(h) * g + b.  One warp per row, float4 per lane.
// ---------------------------------------------------------------------------
__global__ void k_ln(const float* __restrict__ g, const float* __restrict__ b) {
    int warp = (blockIdx.x * blockDim.x + threadIdx.x) >> 5;
    int lane = threadIdx.x & 31;
    if (warp >= N_NODES) return;

    float4 v = ((const float4*)(g_h + (size_t)warp * HID))[lane];
    float s = v.x + v.y + v.z + v.w;
#pragma unroll
    for (int o = 16; o; o >>= 1) s += __shfl_xor_sync(0xFFFFFFFFu, s, o);
    float mu = s * (1.0f / HID);

    float dx = v.x - mu, dy = v.y - mu, dz = v.z - mu, dw = v.w - mu;
    float q = dx * dx + dy * dy + dz * dz + dw * dw;
#pragma unroll
    for (int o = 16; o; o >>= 1) q += __shfl_xor_sync(0xFFFFFFFFu, q, o);
    float rs = rsqrtf(q * (1.0f / HID) + LN_EPS);

    int c = lane * 4;
    float4 gg = *(const float4*)(g + c);
    float4 bb = *(const float4*)(b + c);
    float4 o4;
    o4.x = dx * rs * gg.x + bb.x;
    o4.y = dy * rs * gg.y + bb.y;
    o4.z = dz * rs * gg.z + bb.z;
    o4.w = dw * rs * gg.w + bb.w;
    ((float4*)(g_hn + (size_t)warp * HID))[lane] = o4;
}

// ---------------------------------------------------------------------------
// Aggregate (CSR): agg[n] = (sum over incoming edges of hn[src]) * inv_deg[n]
// One warp per node; lane covers a float4 of the 128-dim row.
// ---------------------------------------------------------------------------
__global__ void k_agg() {
    int node = (blockIdx.x * blockDim.x + threadIdx.x) >> 5;
    int lane = threadIdx.x & 31;
    if (node >= N_NODES) return;

    int beg = g_off[node];
    int end = g_off[node + 1];
    float4 acc = make_float4(0.f, 0.f, 0.f, 0.f);

    for (int e = beg; e < end; e += 32) {
        int rem = end - e;
        int sidx = (lane < rem) ? g_esrc[e + lane] : 0;
        int cnt = rem < 32 ? rem : 32;
#pragma unroll 4
        for (int j = 0; j < cnt; j++) {
            int s = __shfl_sync(0xFFFFFFFFu, sidx, j);
            float4 v = ((const float4*)(g_hn + (size_t)s * HID))[lane];
            acc.x += v.x; acc.y += v.y; acc.z += v.z; acc.w += v.w;
        }
    }

    float inv = g_inv[node];
    acc.x *= inv; acc.y *= inv; acc.z *= inv; acc.w *= inv;
    ((float4*)(g_agg + (size_t)node * HID))[lane] = acc;
}

// ---------------------------------------------------------------------------
// Layer update GEMM: h = relu(h + [agg | hn] @ [Wl ; Wr] + bl)
// A: [N, 256] virtual (agg pre-scaled). 128x128 tile, BK=16, 8x8 microtile,
// split columns (tx*4 and 64+tx*4) for conflict-free LDS.128.
// ---------------------------------------------------------------------------
#define BM 128
#define BKK 16

__global__ void __launch_bounds__(256) k_layer(const float* __restrict__ Wl,
                                               const float* __restrict__ Wr,
                                               const float* __restrict__ bl) {
    __shared__ float As[BKK][BM + 4];
    __shared__ float Bs[BKK][HID];

    int tid = threadIdx.x;
    int tx = tid & 15;    // col pair: tx*4 and 64+tx*4
    int ty = tid >> 4;    // rows ty*8 .. ty*8+7
    int m0 = blockIdx.x * BM;

    float acc[8][8];
#pragma unroll
    for (int i = 0; i < 8; i++)
#pragma unroll
        for (int j = 0; j < 8; j++) acc[i][j] = 0.0f;

    for (int kt = 0; kt < 2 * HID; kt += BKK) {
        const float* Asrc = (kt < HID) ? (g_agg + kt) : (g_hn + (kt - HID));
        const float* Bsrc = (kt < HID) ? (Wl + kt * HID) : (Wr + (kt - HID) * HID);

        // A tile: 128x16 = 512 float4, 2 per thread, store transposed
#pragma unroll
        for (int i = 0; i < 2; i++) {
            int idx = tid + i * 256;
            int m = idx >> 2;
            int k4 = idx & 3;
            int row = m0 + m;
            float4 v = make_float4(0.f, 0.f, 0.f, 0.f);
            if (row < N_NODES) v = *(const float4*)(Asrc + (size_t)row * HID + k4 * 4);
            As[k4 * 4 + 0][m] = v.x;
            As[k4 * 4 + 1][m] = v.y;
            As[k4 * 4 + 2][m] = v.z;
            As[k4 * 4 + 3][m] = v.w;
        }
        // B tile: 16x128 = 512 float4, 2 per thread
#pragma unroll
        for (int i = 0; i < 2; i++) {
            int idx = tid + i * 256;
            int k = idx >> 5;
            int n4 = idx & 31;
            *(float4*)&Bs[k][n4 * 4] = *(const float4*)(Bsrc + k * HID + n4 * 4);
        }
        __syncthreads();

#pragma unroll
        for (int k = 0; k < BKK; k++) {
            float4 a0 = *(const float4*)&As[k][ty * 8];
            float4 a1 = *(const float4*)&As[k][ty * 8 + 4];
            float4 b0 = *(const float4*)&Bs[k][tx * 4];
            float4 b1 = *(const float4*)&Bs[k][64 + tx * 4];
            float a[8] = {a0.x, a0.y, a0.z, a0.w, a1.x, a1.y, a1.z, a1.w};
            float b[8] = {b0.x, b0.y, b0.z, b0.w, b1.x, b1.y, b1.z, b1.w};
#pragma unroll
            for (int i = 0; i < 8; i++)
#pragma unroll
                for (int j = 0; j < 8; j++) acc[i][j] += a[i] * b[j];
        }
        __syncthreads();
    }

    // Epilogue: residual + bias + relu (cols tx*4 and 64+tx*4)
    float4 bb0 = *(const float4*)(bl + tx * 4);
    float4 bb1 = *(const float4*)(bl + 64 + tx * 4);
#pragma unroll
    for (int i = 0; i < 8; i++) {
        int row = m0 + ty * 8 + i;
        if (row >= N_NODES) continue;
        float* hp = g_h + (size_t)row * HID;
        float4 h0 = *(float4*)(hp + tx * 4);
        float4 h1 = *(float4*)(hp + 64 + tx * 4);
        float4 o0, o1;
        o0.x = fmaxf(h0.x + acc[i][0] + bb0.x, 0.0f);
        o0.y = fmaxf(h0.y + acc[i][1] + bb0.y, 0.0f);
        o0.z = fmaxf(h0.z + acc[i][2] + bb0.z, 0.0f);
        o0.w = fmaxf(h0.w + acc[i][3] + bb0.w, 0.0f);
        o1.x = fmaxf(h1.x + acc[i][4] + bb1.x, 0.0f);
        o1.y = fmaxf(h1.y + acc[i][5] + bb1.y, 0.0f);
        o1.z = fmaxf(h1.z + acc[i][6] + bb1.z, 0.0f);
        o1.w = fmaxf(h1.w + acc[i][7] + bb1.w, 0.0f);
        *(float4*)(hp + tx * 4) = o0;
        *(float4*)(hp + 64 + tx * 4) = o1;
    }
}

// ---------------------------------------------------------------------------
// out = h @ W_out + b_out   (50000 x 128 @ 128 x 4), one warp per node
// ---------------------------------------------------------------------------
__global__ void k_out(const float* __restrict__ Wo,
                      const float* __restrict__ bo,
                      float* __restrict__ out) {
    __shared__ float Ws[HID * D_OUT];
    int tid = threadIdx.x;
    for (int i = tid; i < HID * D_OUT; i += blockDim.x) Ws[i] = Wo[i];
    __syncthreads();

    int warp = (blockIdx.x * blockDim.x + tid) >> 5;
    int lane = tid & 31;
    if (warp >= N_NODES) return;

    const float* hr = g_h + (size_t)warp * HID;
    float a0 = 0.f, a1 = 0.f, a2 = 0.f, a3 = 0.f;
#pragma unroll
    for (int t = 0; t < 4; t++) {
        int k = lane + t * 32;
        float hv = hr[k];
        a0 += hv * Ws[k * D_OUT + 0];
        a1 += hv * Ws[k * D_OUT + 1];
        a2 += hv * Ws[k * D_OUT + 2];
        a3 += hv * Ws[k * D_OUT + 3];
    }
#pragma unroll
    for (int o = 16; o; o >>= 1) {
        a0 += __shfl_xor_sync(0xFFFFFFFFu, a0, o);
        a1 += __shfl_xor_sync(0xFFFFFFFFu, a1, o);
        a2 += __shfl_xor_sync(0xFFFFFFFFu, a2, o);
        a3 += __shfl_xor_sync(0xFFFFFFFFu, a3, o);
    }
    if (lane == 0) {
        float4 r;
        r.x = a0 + bo[0];
        r.y = a1 + bo[1];
        r.z = a2 + bo[2];
        r.w = a3 + bo[3];
        *(float4*)(out + (size_t)warp * D_OUT) = r;
    }
}

// ---------------------------------------------------------------------------
extern "C" void kernel_launch(void* const* d_in, const int* in_sizes, int n_in,
                              void* d_out, int out_size) {
    const float* x     = (const float*)d_in[0];
    const int*   ei    = (const int*)  d_in[1];
    const float* W_in  = (const float*)d_in[2];
    const float* b_in  = (const float*)d_in[3];
    const float* Wl    = (const float*)d_in[4];
    const float* bl    = (const float*)d_in[5];
    const float* Wr    = (const float*)d_in[6];
    const float* ln_g  = (const float*)d_in[7];
    const float* ln_b  = (const float*)d_in[8];
    const float* W_out = (const float*)d_in[9];
    const float* b_out = (const float*)d_in[10];
    float* out = (float*)d_out;

    const int* src = ei;             // edge_index[0]
    const int* dst = ei + N_EDGES;   // edge_index[1]

    // CSR build
    k_zero_cnt<<<(N_NODES + 255) / 256, 256>>>();
    k_count<<<(N_EDGES + 255) / 256, 256>>>(dst);
    k_scan1<<<SCAN_BLOCKS, 256>>>();
    k_scan2<<<1, 256>>>();
    k_scan3<<<SCAN_BLOCKS, 256>>>();
    k_fill<<<(N_EDGES + 255) / 256, 256>>>(src, dst);

    k_in_gemm<<<N_NODES / 16, 256>>>(x, W_in, b_in);

    for (int l = 0; l < N_LAYERS; l++) {
        k_ln<<<(N_NODES * 32 + 255) / 256, 256>>>(ln_g + l * HID, ln_b + l * HID);
        k_agg<<<(N_NODES * 32 + 255) / 256, 256>>>();
        k_layer<<<(N_NODES + BM - 1) / BM, 256>>>(Wl + l * HID * HID,
                                                  Wr + l * HID * HID,
                                                  bl + l * HID);
    }

    k_out<<<(N_NODES * 32 + 255) / 256, 256>>>(W_out, b_out, out);
}

// round 5
// speedup vs baseline: 2.9358x; 1.4643x over previous
#include <cuda_runtime.h>
#include <cuda_bf16.h>
#include <cstdint>

#define N_NODES 50000
#define N_EDGES 800000
#define D_IN    16
#define HID     128
#define D_OUT   4
#define N_LAYERS 3
#define LN_EPS  1e-5f

#define SCAN_BLOCKS 196   // ceil(50000/256)

// Scratch (device globals: allocation-free, graph-capturable)
__device__ float g_h   [N_NODES * HID];
__device__ float g_hn  [N_NODES * HID];
__device__ float g_agg [N_NODES * HID];
__device__ __nv_bfloat16 g_Bhi[N_LAYERS * HID * 2 * HID];  // [l][n=128][k=256]
__device__ __nv_bfloat16 g_Blo[N_LAYERS * HID * 2 * HID];
__device__ float g_inv [N_NODES];
__device__ int   g_cnt [N_NODES];
__device__ int   g_off [N_NODES + 1];
__device__ int   g_cur [N_NODES];
__device__ int   g_bsum[SCAN_BLOCKS];
__device__ int   g_bpre[SCAN_BLOCKS];
__device__ int   g_esrc[N_EDGES];

// ---------------------------------------------------------------------------
// bf16 mma.sync (base PTX, works on compute_103): D += A(16x16) * B(16x8)
// ---------------------------------------------------------------------------
__device__ __forceinline__ void mma_bf16(float* c, const uint32_t* a, const uint32_t* b) {
    asm volatile(
        "mma.sync.aligned.m16n8k16.row.col.f32.bf16.bf16.f32 "
        "{%0,%1,%2,%3}, {%4,%5,%6,%7}, {%8,%9}, {%0,%1,%2,%3};"
        : "+f"(c[0]), "+f"(c[1]), "+f"(c[2]), "+f"(c[3])
        : "r"(a[0]), "r"(a[1]), "r"(a[2]), "r"(a[3]), "r"(b[0]), "r"(b[1]));
}

// ---------------------------------------------------------------------------
// CSR build: histogram -> scan -> fill
// ---------------------------------------------------------------------------
__global__ void k_zero_cnt() {
    int i = blockIdx.x * blockDim.x + threadIdx.x;
    if (i < N_NODES) g_cnt[i] = 0;
}

__global__ void k_count(const int* __restrict__ dst) {
    int e = blockIdx.x * blockDim.x + threadIdx.x;
    if (e < N_EDGES) atomicAdd(&g_cnt[dst[e]], 1);
}

__global__ void k_scan1() {
    __shared__ int s[2][256];
    int b = blockIdx.x, t = threadIdx.x;
    int i = b * 256 + t;
    int v = (i < N_NODES) ? g_cnt[i] : 0;
    s[0][t] = v;
    __syncthreads();
    int p = 0;
#pragma unroll
    for (int off = 1; off < 256; off <<= 1) {
        int nv = s[p][t] + ((t >= off) ? s[p][t - off] : 0);
        s[p ^ 1][t] = nv;
        __syncthreads();
        p ^= 1;
    }
    if (i < N_NODES) g_off[i] = s[p][t] - v;
    if (t == 255) g_bsum[b] = s[p][255];
}

__global__ void k_scan2() {
    __shared__ int s[2][256];
    int t = threadIdx.x;
    int v = (t < SCAN_BLOCKS) ? g_bsum[t] : 0;
    s[0][t] = v;
    __syncthreads();
    int p = 0;
#pragma unroll
    for (int off = 1; off < 256; off <<= 1) {
        int nv = s[p][t] + ((t >= off) ? s[p][t - off] : 0);
        s[p ^ 1][t] = nv;
        __syncthreads();
        p ^= 1;
    }
    if (t < SCAN_BLOCKS) g_bpre[t] = s[p][t] - v;
}

__global__ void k_scan3() {
    int i = blockIdx.x * blockDim.x + threadIdx.x;
    if (i < N_NODES) {
        int o = g_off[i] + g_bpre[i >> 8];
        g_off[i] = o;
        g_cur[i] = o;
        g_inv[i] = 1.0f / fmaxf((float)g_cnt[i], 1.0f);
    }
    if (i == 0) g_off[N_NODES] = N_EDGES;
}

__global__ void k_fill(const int* __restrict__ src, const int* __restrict__ dst) {
    int e = blockIdx.x * blockDim.x + threadIdx.x;
    if (e < N_EDGES) {
        int pos = atomicAdd(&g_cur[dst[e]], 1);
        g_esrc[pos] = src[e];
    }
}

// ---------------------------------------------------------------------------
// Weight transpose + bf16 hi/lo split:
// g_Bhi/lo[l][n][k] from Wcat[k][n] = (k<128 ? Wl[l][k][n] : Wr[l][k-128][n])
// ---------------------------------------------------------------------------
__global__ void k_wsplit(const float* __restrict__ Wl, const float* __restrict__ Wr) {
    __shared__ float s[32][33];
    int K0 = blockIdx.x * 32;
    int N0 = blockIdx.y * 32;
    int l = blockIdx.z;
    int tx = threadIdx.x, ty = threadIdx.y;
    const float* WlL = Wl + l * HID * HID;
    const float* WrL = Wr + l * HID * HID;
#pragma unroll
    for (int i = 0; i < 4; i++) {
        int k = K0 + ty + i * 8;
        int n = N0 + tx;
        s[ty + i * 8][tx] = (k < HID) ? WlL[k * HID + n] : WrL[(k - HID) * HID + n];
    }
    __syncthreads();
    __nv_bfloat16* Oh = g_Bhi + (size_t)l * HID * 2 * HID;
    __nv_bfloat16* Ol = g_Blo + (size_t)l * HID * 2 * HID;
#pragma unroll
    for (int i = 0; i < 4; i++) {
        int n = N0 + ty + i * 8;
        int k = K0 + tx;
        float v = s[tx][ty + i * 8];
        __nv_bfloat16 hi = __float2bfloat16_rn(v);
        Oh[(size_t)n * 256 + k] = hi;
        Ol[(size_t)n * 256 + k] = __float2bfloat16_rn(v - __bfloat162float(hi));
    }
}

// ---------------------------------------------------------------------------
// h = x @ W_in + b_in    (50000 x 16 @ 16 x 128)
// ---------------------------------------------------------------------------
__global__ void k_in_gemm(const float* __restrict__ x,
                          const float* __restrict__ W,
                          const float* __restrict__ b) {
    __shared__ float xs[16][D_IN];
    __shared__ float Ws[D_IN][HID];
    int tid = threadIdx.x;
    int m0 = blockIdx.x * 16;

#pragma unroll
    for (int i = 0; i < 2; i++) {
        int idx = tid + i * 256;
        ((float4*)&Ws[0][0])[idx] = ((const float4*)W)[idx];
    }
    {
        int r = tid >> 4, k = tid & 15;
        xs[r][k] = x[(size_t)(m0 + r) * D_IN + k];
    }
    __syncthreads();

    int col = tid & 127;
    int rh  = tid >> 7;
    float wc[D_IN];
#pragma unroll
    for (int k = 0; k < D_IN; k++) wc[k] = Ws[k][col];
    float bb = b[col];

#pragma unroll
    for (int r = 0; r < 8; r++) {
        int row = rh * 8 + r;
        float acc = bb;
#pragma unroll
        for (int k = 0; k < D_IN; k++) acc += xs[row][k] * wc[k];
        g_h[(size_t)(m0 + row) * HID + col] = acc;
    }
}

// ---------------------------------------------------------------------------
// LayerNorm: hn = LN(h) * g + b.  One warp per row, float4 per lane.
// ---------------------------------------------------------------------------
__global__ void k_ln(const float* __restrict__ g, const float* __restrict__ b) {
    int warp = (blockIdx.x * blockDim.x + threadIdx.x) >> 5;
    int lane = threadIdx.x & 31;
    if (warp >= N_NODES) return;

    float4 v = ((const float4*)(g_h + (size_t)warp * HID))[lane];
    float s = v.x + v.y + v.z + v.w;
#pragma unroll
    for (int o = 16; o; o >>= 1) s += __shfl_xor_sync(0xFFFFFFFFu, s, o);
    float mu = s * (1.0f / HID);

    float dx = v.x - mu, dy = v.y - mu, dz = v.z - mu, dw = v.w - mu;
    float q = dx * dx + dy * dy + dz * dz + dw * dw;
#pragma unroll
    for (int o = 16; o; o >>= 1) q += __shfl_xor_sync(0xFFFFFFFFu, q, o);
    float rs = rsqrtf(q * (1.0f / HID) + LN_EPS);

    int c = lane * 4;
    float4 gg = *(const float4*)(g + c);
    float4 bb = *(const float4*)(b + c);
    float4 o4;
    o4.x = dx * rs * gg.x + bb.x;
    o4.y = dy * rs * gg.y + bb.y;
    o4.z = dz * rs * gg.z + bb.z;
    o4.w = dw * rs * gg.w + bb.w;
    ((float4*)(g_hn + (size_t)warp * HID))[lane] = o4;
}

// ---------------------------------------------------------------------------
// Aggregate (CSR): agg[n] = (sum over incoming edges of hn[src]) * inv_deg[n]
// ---------------------------------------------------------------------------
__global__ void k_agg() {
    int node = (blockIdx.x * blockDim.x + threadIdx.x) >> 5;
    int lane = threadIdx.x & 31;
    if (node >= N_NODES) return;

    int beg = g_off[node];
    int end = g_off[node + 1];
    float4 acc = make_float4(0.f, 0.f, 0.f, 0.f);

    for (int e = beg; e < end; e += 32) {
        int rem = end - e;
        int sidx = (lane < rem) ? g_esrc[e + lane] : 0;
        int cnt = rem < 32 ? rem : 32;
#pragma unroll 4
        for (int j = 0; j < cnt; j++) {
            int s = __shfl_sync(0xFFFFFFFFu, sidx, j);
            float4 v = ((const float4*)(g_hn + (size_t)s * HID))[lane];
            acc.x += v.x; acc.y += v.y; acc.z += v.z; acc.w += v.w;
        }
    }

    float inv = g_inv[node];
    acc.x *= inv; acc.y *= inv; acc.z *= inv; acc.w *= inv;
    ((float4*)(g_agg + (size_t)node * HID))[lane] = acc;
}

// ---------------------------------------------------------------------------
// Layer GEMM via mma.sync bf16x3:  h = relu(h + [agg | hn] @ Wcat + bl)
// CTA tile 128(M)x128(N), K=256 in 16 chunks of 16. 512 threads = 16 warps,
// warp grid 4(m)x4(n), warp tile 32x32 (2 m-frags x 4 n-frags).
// 2-stage smem double buffer, 48B row pitch (conflict-free quad-pair LDS).
// ---------------------------------------------------------------------------
#define LPITCH 48
#define STG    6144          // 128 rows * 48B, one stage of one array
#define SM_A_HI 0
#define SM_A_LO 12288
#define SM_B_HI 24576
#define SM_B_LO 36864
#define LAYER_SMEM 49152

__global__ void __launch_bounds__(512) k_layer(int l, const float* __restrict__ bl) {
    extern __shared__ char sm[];
    int tid = threadIdx.x;
    int lane = tid & 31, wid = tid >> 5;
    int wm = wid & 3, wn = wid >> 2;
    int m0 = blockIdx.x * 128;

    const __nv_bfloat16* Bh_ = g_Bhi + (size_t)l * HID * 2 * HID;
    const __nv_bfloat16* Bl_ = g_Blo + (size_t)l * HID * 2 * HID;

    float C[2][4][4];
#pragma unroll
    for (int mt = 0; mt < 2; mt++)
#pragma unroll
        for (int nt = 0; nt < 4; nt++)
#pragma unroll
            for (int j = 0; j < 4; j++) C[mt][nt][j] = 0.0f;

    // staging mapping: A: row = tid>>2, float4 q = tid&3 (chunk is 128x16 fp32)
    //                  B: n-row = tid>>2, uint2 q = tid&3 (chunk is 128x16 bf16)
    int s_r = tid >> 2, s_q = tid & 3;
    int arow = m0 + s_r;
    if (arow >= N_NODES) arow = N_NODES - 1;

    float4 av;
    uint2 bhv, blv;
    // prefetch chunk 0 (A from g_agg cols 0..15)
    av  = *(const float4*)(g_agg + (size_t)arow * HID + s_q * 4);
    bhv = *(const uint2*)(Bh_ + (size_t)s_r * 256 + s_q * 4);
    blv = *(const uint2*)(Bl_ + (size_t)s_r * 256 + s_q * 4);

    for (int c = 0; c < 16; c++) {
        int st = c & 1;
        char* Ah = sm + SM_A_HI + st * STG;
        char* Al = sm + SM_A_LO + st * STG;
        char* Bh = sm + SM_B_HI + st * STG;
        char* Bl = sm + SM_B_LO + st * STG;

        // convert + store staged regs
        {
            __nv_bfloat162 h0 = __floats2bfloat162_rn(av.x, av.y);
            __nv_bfloat162 h1 = __floats2bfloat162_rn(av.z, av.w);
            float lx = av.x - __bfloat162float(h0.x);
            float ly = av.y - __bfloat162float(h0.y);
            float lz = av.z - __bfloat162float(h1.x);
            float lw = av.w - __bfloat162float(h1.y);
            __nv_bfloat162 l0 = __floats2bfloat162_rn(lx, ly);
            __nv_bfloat162 l1 = __floats2bfloat162_rn(lz, lw);
            uint2 ph, pl;
            ph.x = *(uint32_t*)&h0; ph.y = *(uint32_t*)&h1;
            pl.x = *(uint32_t*)&l0; pl.y = *(uint32_t*)&l1;
            *(uint2*)(Ah + s_r * LPITCH + s_q * 8) = ph;
            *(uint2*)(Al + s_r * LPITCH + s_q * 8) = pl;
            *(uint2*)(Bh + s_r * LPITCH + s_q * 8) = bhv;
            *(uint2*)(Bl + s_r * LPITCH + s_q * 8) = blv;
        }
        __syncthreads();

        // prefetch next chunk
        if (c < 15) {
            int cn = c + 1;
            const float* Asrc = (cn < 8) ? (g_agg + cn * 16) : (g_hn + (cn - 8) * 16);
            av  = *(const float4*)(Asrc + (size_t)arow * HID + s_q * 4);
            bhv = *(const uint2*)(Bh_ + (size_t)s_r * 256 + cn * 16 + s_q * 4);
            blv = *(const uint2*)(Bl_ + (size_t)s_r * 256 + cn * 16 + s_q * 4);
        }

        // load fragments
        uint32_t a_hi[2][4], a_lo[2][4], b_hi[4][2], b_lo[4][2];
#pragma unroll
        for (int mt = 0; mt < 2; mt++) {
            int off = (wm * 32 + mt * 16 + (lane >> 2)) * LPITCH + (lane & 3) * 4;
            a_hi[mt][0] = *(uint32_t*)(Ah + off);
            a_hi[mt][1] = *(uint32_t*)(Ah + off + 8 * LPITCH);
            a_hi[mt][2] = *(uint32_t*)(Ah + off + 16);
            a_hi[mt][3] = *(uint32_t*)(Ah + off + 8 * LPITCH + 16);
            a_lo[mt][0] = *(uint32_t*)(Al + off);
            a_lo[mt][1] = *(uint32_t*)(Al + off + 8 * LPITCH);
            a_lo[mt][2] = *(uint32_t*)(Al + off + 16);
            a_lo[mt][3] = *(uint32_t*)(Al + off + 8 * LPITCH + 16);
        }
#pragma unroll
        for (int nt = 0; nt < 4; nt++) {
            int off = (wn * 32 + nt * 8 + (lane >> 2)) * LPITCH + (lane & 3) * 4;
            b_hi[nt][0] = *(uint32_t*)(Bh + off);
            b_hi[nt][1] = *(uint32_t*)(Bh + off + 16);
            b_lo[nt][0] = *(uint32_t*)(Bl + off);
            b_lo[nt][1] = *(uint32_t*)(Bl + off + 16);
        }

#pragma unroll
        for (int mt = 0; mt < 2; mt++)
#pragma unroll
            for (int nt = 0; nt < 4; nt++) {
                mma_bf16(C[mt][nt], a_hi[mt], b_hi[nt]);
                mma_bf16(C[mt][nt], a_hi[mt], b_lo[nt]);
                mma_bf16(C[mt][nt], a_lo[mt], b_hi[nt]);
            }
        __syncthreads();
    }

    // Epilogue: residual + bias + relu into g_h
#pragma unroll
    for (int mt = 0; mt < 2; mt++) {
        int r0 = m0 + wm * 32 + mt * 16 + (lane >> 2);
#pragma unroll
        for (int half = 0; half < 2; half++) {
            int r = r0 + half * 8;
            if (r < N_NODES) {
#pragma unroll
                for (int nt = 0; nt < 4; nt++) {
                    int cb = wn * 32 + nt * 8 + (lane & 3) * 2;
                    float* hp = g_h + (size_t)r * HID + cb;
                    float2 h2 = *(float2*)hp;
                    float2 bb = *(const float2*)(bl + cb);
                    float2 o;
                    o.x = fmaxf(h2.x + C[mt][nt][half * 2 + 0] + bb.x, 0.0f);
                    o.y = fmaxf(h2.y + C[mt][nt][half * 2 + 1] + bb.y, 0.0f);
                    *(float2*)hp = o;
                }
            }
        }
    }
}

// ---------------------------------------------------------------------------
// out = h @ W_out + b_out   (50000 x 128 @ 128 x 4), one warp per node
// ---------------------------------------------------------------------------
__global__ void k_out(const float* __restrict__ Wo,
                      const float* __restrict__ bo,
                      float* __restrict__ out) {
    __shared__ float Ws[HID * D_OUT];
    int tid = threadIdx.x;
    for (int i = tid; i < HID * D_OUT; i += blockDim.x) Ws[i] = Wo[i];
    __syncthreads();

    int warp = (blockIdx.x * blockDim.x + tid) >> 5;
    int lane = tid & 31;
    if (warp >= N_NODES) return;

    const float* hr = g_h + (size_t)warp * HID;
    float a0 = 0.f, a1 = 0.f, a2 = 0.f, a3 = 0.f;
#pragma unroll
    for (int t = 0; t < 4; t++) {
        int k = lane + t * 32;
        float hv = hr[k];
        a0 += hv * Ws[k * D_OUT + 0];
        a1 += hv * Ws[k * D_OUT + 1];
        a2 += hv * Ws[k * D_OUT + 2];
        a3 += hv * Ws[k * D_OUT + 3];
    }
#pragma unroll
    for (int o = 16; o; o >>= 1) {
        a0 += __shfl_xor_sync(0xFFFFFFFFu, a0, o);
        a1 += __shfl_xor_sync(0xFFFFFFFFu, a1, o);
        a2 += __shfl_xor_sync(0xFFFFFFFFu, a2, o);
        a3 += __shfl_xor_sync(0xFFFFFFFFu, a3, o);
    }
    if (lane == 0) {
        float4 r;
        r.x = a0 + bo[0];
        r.y = a1 + bo[1];
        r.z = a2 + bo[2];
        r.w = a3 + bo[3];
        *(float4*)(out + (size_t)warp * D_OUT) = r;
    }
}

// ---------------------------------------------------------------------------
extern "C" void kernel_launch(void* const* d_in, const int* in_sizes, int n_in,
                              void* d_out, int out_size) {
    const float* x     = (const float*)d_in[0];
    const int*   ei    = (const int*)  d_in[1];
    const float* W_in  = (const float*)d_in[2];
    const float* b_in  = (const float*)d_in[3];
    const float* Wl    = (const float*)d_in[4];
    const float* bl    = (const float*)d_in[5];
    const float* Wr    = (const float*)d_in[6];
    const float* ln_g  = (const float*)d_in[7];
    const float* ln_b  = (const float*)d_in[8];
    const float* W_out = (const float*)d_in[9];
    const float* b_out = (const float*)d_in[10];
    float* out = (float*)d_out;

    const int* src = ei;             // edge_index[0]
    const int* dst = ei + N_EDGES;   // edge_index[1]

    cudaFuncSetAttribute(k_layer, cudaFuncAttributeMaxDynamicSharedMemorySize, LAYER_SMEM);

    // CSR build
    k_zero_cnt<<<(N_NODES + 255) / 256, 256>>>();
    k_count<<<(N_EDGES + 255) / 256, 256>>>(dst);
    k_scan1<<<SCAN_BLOCKS, 256>>>();
    k_scan2<<<1, 256>>>();
    k_scan3<<<SCAN_BLOCKS, 256>>>();
    k_fill<<<(N_EDGES + 255) / 256, 256>>>(src, dst);

    // Weight transpose + bf16 hi/lo split (once per call)
    {
        dim3 g(256 / 32, 128 / 32, N_LAYERS);
        dim3 b(32, 8);
        k_wsplit<<<g, b>>>(Wl, Wr);
    }

    k_in_gemm<<<N_NODES / 16, 256>>>(x, W_in, b_in);

    for (int l = 0; l < N_LAYERS; l++) {
        k_ln<<<(N_NODES * 32 + 255) / 256, 256>>>(ln_g + l * HID, ln_b + l * HID);
        k_agg<<<(N_NODES * 32 + 255) / 256, 256>>>();
        k_layer<<<(N_NODES + 127) / 128, 512, LAYER_SMEM>>>(l, bl + l * HID);
    }

    k_out<<<(N_NODES * 32 + 255) / 256, 256>>>(W_out, b_out, out);
}